// round 1
// baseline (speedup 1.0000x reference)
#include <cuda_runtime.h>
#include <math.h>

#define B_SZ   4
#define S_LEN  2048
#define D_DIM  1024
#define NH     16
#define HD_    64
#define QKV_LD 3072
#define BQ     64
#define BK     64

// Scratch (no runtime allocation allowed).
__device__ float g_qkv[(size_t)B_SZ * S_LEN * QKV_LD]; // [B*S, 3D]
__device__ float g_att[(size_t)B_SZ * S_LEN * D_DIM];  // [B*S, D] attention out

// ---------------------------------------------------------------------------
// SGEMM (NT): C[M,N] = A[M,K] * B[N,K]^T, row-major, M%128==0, N%128==0, K%8==0
// 256 threads, 128x128 tile, 8x8 per-thread micro-tile.
// ---------------------------------------------------------------------------
__global__ __launch_bounds__(256, 2)
void sgemm_nt(const float* __restrict__ A, const float* __restrict__ B,
              float* __restrict__ C, int M, int N, int K) {
    __shared__ __align__(16) float As[8][128];
    __shared__ __align__(16) float Bs[8][128];

    const int tid  = threadIdx.x;
    const int tx   = tid & 15;
    const int ty   = tid >> 4;
    const int row0 = blockIdx.y << 7;
    const int col0 = blockIdx.x << 7;

    // Loader mapping: each thread loads one float4 of A and one of B per k-step.
    const int lr = tid >> 1;           // 0..127 (tile row)
    const int lk = (tid & 1) << 2;     // 0 or 4 (k offset)

    float c[8][8];
#pragma unroll
    for (int i = 0; i < 8; i++)
#pragma unroll
        for (int j = 0; j < 8; j++) c[i][j] = 0.f;

    for (int k0 = 0; k0 < K; k0 += 8) {
        float4 av = *(const float4*)(A + (size_t)(row0 + lr) * K + k0 + lk);
        float4 bv = *(const float4*)(B + (size_t)(col0 + lr) * K + k0 + lk);
        __syncthreads();   // previous tile's compute done before overwrite
        As[lk + 0][lr] = av.x; As[lk + 1][lr] = av.y;
        As[lk + 2][lr] = av.z; As[lk + 3][lr] = av.w;
        Bs[lk + 0][lr] = bv.x; Bs[lk + 1][lr] = bv.y;
        Bs[lk + 2][lr] = bv.z; Bs[lk + 3][lr] = bv.w;
        __syncthreads();
#pragma unroll
        for (int kk = 0; kk < 8; kk++) {
            float4 a0 = *(const float4*)&As[kk][ty * 8];
            float4 a1 = *(const float4*)&As[kk][ty * 8 + 4];
            float4 b0 = *(const float4*)&Bs[kk][tx * 8];
            float4 b1 = *(const float4*)&Bs[kk][tx * 8 + 4];
            float ra[8] = {a0.x, a0.y, a0.z, a0.w, a1.x, a1.y, a1.z, a1.w};
            float rb[8] = {b0.x, b0.y, b0.z, b0.w, b1.x, b1.y, b1.z, b1.w};
#pragma unroll
            for (int i = 0; i < 8; i++)
#pragma unroll
                for (int j = 0; j < 8; j++)
                    c[i][j] += ra[i] * rb[j];
        }
    }

#pragma unroll
    for (int i = 0; i < 8; i++)
#pragma unroll
        for (int j = 0; j < 8; j += 4) {
            float4 v = make_float4(c[i][j], c[i][j + 1], c[i][j + 2], c[i][j + 3]);
            *(float4*)(C + (size_t)(row0 + ty * 8 + i) * N + col0 + tx * 8 + j) = v;
        }
}

// ---------------------------------------------------------------------------
// Causal flash attention, fp32.
// grid: (S/64, B*H); block: 256 threads as 16(tx) x 16(ty).
// Each thread owns a 4x4 micro-tile: rows ty*4..+4 (queries), cols tx*4..+4
// (keys for scores / head dims for output). Online softmax; row stats
// replicated across the 16 tx lanes (shuffle reductions over a 16-lane group).
// Q,K in smem (float4-XOR swizzle), P in smem (warp-private rows), V via LDG
// (tile is L1-resident). Static smem = 48 KB exactly.
// ---------------------------------------------------------------------------
__global__ __launch_bounds__(256, 2)
void attn_fwd(const float* __restrict__ qkv, float* __restrict__ out) {
    __shared__ __align__(16) float Qs[BQ * HD_];
    __shared__ __align__(16) float Ks[BK * HD_];
    __shared__ __align__(16) float Ps[BQ * BK];

    const int bh = blockIdx.y;
    const int b  = bh >> 4;
    const int h  = bh & 15;
    const int q0 = blockIdx.x << 6;

    const int tid = threadIdx.x;
    const int tx  = tid & 15;
    const int ty  = tid >> 4;

    const size_t row_base = (size_t)b * S_LEN;
    const unsigned FULL = 0xffffffffu;

    // ---- load Q tile (swizzled, float4) ----
#pragma unroll
    for (int i = tid; i < BQ * 16; i += 256) {
        int r = i >> 4, v = i & 15;
        float4 q = *(const float4*)(qkv + (row_base + q0 + r) * QKV_LD + h * HD_ + v * 4);
        ((float4*)Qs)[r * 16 + (v ^ (r & 7))] = q;
    }

    float m[4], l[4], o[4][4];
#pragma unroll
    for (int i = 0; i < 4; i++) {
        m[i] = -1e30f; l[i] = 0.f;
#pragma unroll
        for (int j = 0; j < 4; j++) o[i][j] = 0.f;
    }

    const int qb[4] = {(ty * 4 + 0) * 16, (ty * 4 + 1) * 16,
                       (ty * 4 + 2) * 16, (ty * 4 + 3) * 16};
    const int qx[4] = {(ty * 4 + 0) & 7, (ty * 4 + 1) & 7,
                       (ty * 4 + 2) & 7, (ty * 4 + 3) & 7};
    const int kb[4] = {(tx * 4 + 0) * 16, (tx * 4 + 1) * 16,
                       (tx * 4 + 2) * 16, (tx * 4 + 3) * 16};
    const int kx[4] = {(tx * 4 + 0) & 7, (tx * 4 + 1) & 7,
                       (tx * 4 + 2) & 7, (tx * 4 + 3) & 7};

    for (int k0 = 0; k0 < q0 + BQ; k0 += BK) {
        // ---- load K tile (swizzled, float4) ----
#pragma unroll
        for (int i = tid; i < BK * 16; i += 256) {
            int r = i >> 4, v = i & 15;
            float4 kx4 = *(const float4*)(qkv + (row_base + k0 + r) * QKV_LD +
                                          D_DIM + h * HD_ + v * 4);
            ((float4*)Ks)[r * 16 + (v ^ (r & 7))] = kx4;
        }
        __syncthreads();

        // ---- scores: 4x4 per thread over HD=64 ----
        float acc[4][4];
#pragma unroll
        for (int i = 0; i < 4; i++)
#pragma unroll
            for (int j = 0; j < 4; j++) acc[i][j] = 0.f;

#pragma unroll
        for (int v = 0; v < 16; v++) {
            float4 qv[4], kv[4];
#pragma unroll
            for (int i = 0; i < 4; i++)
                qv[i] = ((const float4*)Qs)[qb[i] + (v ^ qx[i])];
#pragma unroll
            for (int j = 0; j < 4; j++)
                kv[j] = ((const float4*)Ks)[kb[j] + (v ^ kx[j])];
#pragma unroll
            for (int i = 0; i < 4; i++)
#pragma unroll
                for (int j = 0; j < 4; j++)
                    acc[i][j] += qv[i].x * kv[j].x + qv[i].y * kv[j].y +
                                 qv[i].z * kv[j].z + qv[i].w * kv[j].w;
        }

        const bool diag = (k0 == q0);
#pragma unroll
        for (int i = 0; i < 4; i++)
#pragma unroll
            for (int j = 0; j < 4; j++) {
                acc[i][j] *= 0.125f;  // 1/sqrt(64)
                if (diag && (tx * 4 + j) > (ty * 4 + i)) acc[i][j] = -1e30f;
            }

        // ---- online softmax update (per row; reduce across 16 tx lanes) ----
#pragma unroll
        for (int i = 0; i < 4; i++) {
            float mt = fmaxf(fmaxf(acc[i][0], acc[i][1]),
                             fmaxf(acc[i][2], acc[i][3]));
            mt = fmaxf(mt, __shfl_xor_sync(FULL, mt, 1));
            mt = fmaxf(mt, __shfl_xor_sync(FULL, mt, 2));
            mt = fmaxf(mt, __shfl_xor_sync(FULL, mt, 4));
            mt = fmaxf(mt, __shfl_xor_sync(FULL, mt, 8));
            float mn   = fmaxf(m[i], mt);
            float corr = __expf(m[i] - mn);
            float sum  = 0.f;
#pragma unroll
            for (int j = 0; j < 4; j++) {
                float p = __expf(acc[i][j] - mn);
                acc[i][j] = p;
                sum += p;
            }
            sum += __shfl_xor_sync(FULL, sum, 1);
            sum += __shfl_xor_sync(FULL, sum, 2);
            sum += __shfl_xor_sync(FULL, sum, 4);
            sum += __shfl_xor_sync(FULL, sum, 8);
            l[i] = l[i] * corr + sum;
            m[i] = mn;
#pragma unroll
            for (int j = 0; j < 4; j++) o[i][j] *= corr;
        }

        // ---- stash P (rows are warp-private: same 16-lane group reads them) ----
#pragma unroll
        for (int i = 0; i < 4; i++)
            ((float4*)Ps)[(ty * 4 + i) * 16 + tx] =
                make_float4(acc[i][0], acc[i][1], acc[i][2], acc[i][3]);

        __syncthreads();  // scores done: safe to overwrite Ks next iter; Ps visible

        // ---- O += P @ V  (V streamed via LDG.128, L1-resident tile) ----
#pragma unroll 8
        for (int kk = 0; kk < BK; kk++) {
            float4 vv = *(const float4*)(qkv + (row_base + k0 + kk) * QKV_LD +
                                         2 * D_DIM + h * HD_ + tx * 4);
            float p[4];
#pragma unroll
            for (int i = 0; i < 4; i++) p[i] = Ps[(ty * 4 + i) * 64 + kk];
#pragma unroll
            for (int i = 0; i < 4; i++) {
                o[i][0] += p[i] * vv.x;
                o[i][1] += p[i] * vv.y;
                o[i][2] += p[i] * vv.z;
                o[i][3] += p[i] * vv.w;
            }
        }
    }

    // ---- epilogue: normalize and write [b, s, h*64 + d] ----
#pragma unroll
    for (int i = 0; i < 4; i++) {
        float inv = 1.0f / l[i];
        float4 res = make_float4(o[i][0] * inv, o[i][1] * inv,
                                 o[i][2] * inv, o[i][3] * inv);
        *(float4*)(out + (row_base + q0 + ty * 4 + i) * D_DIM + h * HD_ + tx * 4) = res;
    }
}

// ---------------------------------------------------------------------------
extern "C" void kernel_launch(void* const* d_in, const int* in_sizes, int n_in,
                              void* d_out, int out_size) {
    const float* x      = (const float*)d_in[0];  // [B, S, D]
    const float* w_attn = (const float*)d_in[1];  // [3D, D]
    const float* w_proj = (const float*)d_in[2];  // [D, D]
    float* outp         = (float*)d_out;          // [B, S, D]

    void* p_qkv = nullptr;
    void* p_att = nullptr;
    cudaGetSymbolAddress(&p_qkv, g_qkv);
    cudaGetSymbolAddress(&p_att, g_att);
    float* qkv = (float*)p_qkv;
    float* att = (float*)p_att;

    const int M = B_SZ * S_LEN;  // 8192

    // 1) QKV = X @ W_attn^T : [8192,1024] x [3072,1024]^T
    sgemm_nt<<<dim3(QKV_LD / 128, M / 128), 256>>>(x, w_attn, qkv, M, QKV_LD, D_DIM);

    // 2) causal attention -> att [8192, 1024] (already in (b,s,h,hd) layout)
    attn_fwd<<<dim3(S_LEN / BQ, B_SZ * NH), 256>>>(qkv, att);

    // 3) out = att @ W_proj^T : [8192,1024] x [1024,1024]^T
    sgemm_nt<<<dim3(D_DIM / 128, M / 128), 256>>>(att, w_proj, outp, M, D_DIM, D_DIM);
}

// round 3
// speedup vs baseline: 1.4770x; 1.4770x over previous
#include <cuda_runtime.h>
#include <math.h>
#include <cstdint>

#define B_SZ   4
#define S_LEN  2048
#define D_DIM  1024
#define NH     16
#define HD_    64
#define QKV_LD 3072
#define BQ     64
#define BK     64

// Scratch (no runtime allocation allowed).
__device__ float g_qkv[(size_t)B_SZ * S_LEN * QKV_LD]; // [B*S, 3D]
__device__ float g_att[(size_t)B_SZ * S_LEN * D_DIM];  // [B*S, D] attention out

// ---------------------------------------------------------------------------
// tf32 helpers (target-neutral: mma.sync path, works on plain sm_103 target)
// ---------------------------------------------------------------------------
__device__ __forceinline__ uint32_t cvt_tf32(float f) {
    uint32_t r;
    asm("cvt.rna.tf32.f32 %0, %1;" : "=r"(r) : "f"(f));
    return r;
}

#define MMA_TF32(d0, d1, d2, d3, a0, a1, a2, a3, b0, b1)                      \
    asm volatile(                                                             \
        "mma.sync.aligned.m16n8k8.row.col.f32.tf32.tf32.f32 "                 \
        "{%0,%1,%2,%3}, {%4,%5,%6,%7}, {%8,%9}, {%0,%1,%2,%3};"               \
        : "+f"(d0), "+f"(d1), "+f"(d2), "+f"(d3)                              \
        : "r"(a0), "r"(a1), "r"(a2), "r"(a3), "r"(b0), "r"(b1))

// ---------------------------------------------------------------------------
// Tensor-core SGEMM (tf32 mma.sync, NT): C[M,N] = A[M,K] * B[N,K]^T.
// Row-major; M%128==0, N%128==0, K%32==0.
// 256 threads (8 warps, 2x4), 128x128 CTA tile, per-warp 64x32 (4x4 m16n8k8).
// Double-buffered smem (K-tile 32), 1 syncthreads/tile, reg-prefetch of LDG.
// Smem row stride 36 floats: 16B-aligned rows + conflict-free fragment reads.
// ---------------------------------------------------------------------------
#define SROW 36
#define STAGE (128 * SROW)            // floats per matrix per stage
#define GSMEM_BYTES (4 * STAGE * 4)   // 2 stages x (A+B) = 73728 B

__global__ __launch_bounds__(256)
void sgemm_mma(const float* __restrict__ A, const float* __restrict__ B,
               float* __restrict__ C, int M, int N, int K) {
    extern __shared__ __align__(16) uint32_t sm[];
    // layout: A0 | A1 | B0 | B1, each STAGE uint32
    const int tid  = threadIdx.x;
    const int wid  = tid >> 5;
    const int lane = tid & 31;
    const int g    = lane >> 2;       // 0..7
    const int t    = lane & 3;        // 0..3
    const int row0 = blockIdx.y << 7;
    const int col0 = blockIdx.x << 7;
    const int warp_m = (wid >> 2) * 64;
    const int warp_n = (wid & 3) * 32;

    // loader mapping: thread covers rows rbase+32i, cols 4c..4c+3 of the tile
    const int rbase = tid >> 3;       // 0..31
    const int c4    = (tid & 7) * 4;  // 0,4,..28

    float acc[4][4][4];
#pragma unroll
    for (int i = 0; i < 4; i++)
#pragma unroll
        for (int j = 0; j < 4; j++)
#pragma unroll
            for (int k = 0; k < 4; k++) acc[i][j][k] = 0.f;

    const int KT = K >> 5;
    float4 pa[4], pb[4];

    // prologue: global prefetch of k-tile 0
#pragma unroll
    for (int i = 0; i < 4; i++) {
        pa[i] = *(const float4*)(A + (size_t)(row0 + rbase + 32 * i) * K + c4);
        pb[i] = *(const float4*)(B + (size_t)(col0 + rbase + 32 * i) * K + c4);
    }
    // store stage 0 (with tf32 round)
#pragma unroll
    for (int i = 0; i < 4; i++) {
        uint32_t* ap = sm + (rbase + 32 * i) * SROW + c4;
        uint32_t* bp = sm + 2 * STAGE + (rbase + 32 * i) * SROW + c4;
        ap[0] = cvt_tf32(pa[i].x); ap[1] = cvt_tf32(pa[i].y);
        ap[2] = cvt_tf32(pa[i].z); ap[3] = cvt_tf32(pa[i].w);
        bp[0] = cvt_tf32(pb[i].x); bp[1] = cvt_tf32(pb[i].y);
        bp[2] = cvt_tf32(pb[i].z); bp[3] = cvt_tf32(pb[i].w);
    }
    __syncthreads();

    for (int kt = 0; kt < KT; kt++) {
        // prefetch next k-tile from global while computing this one
        if (kt + 1 < KT) {
            const int kb = (kt + 1) << 5;
#pragma unroll
            for (int i = 0; i < 4; i++) {
                pa[i] = *(const float4*)(A + (size_t)(row0 + rbase + 32 * i) * K + kb + c4);
                pb[i] = *(const float4*)(B + (size_t)(col0 + rbase + 32 * i) * K + kb + c4);
            }
        }

        const uint32_t* Asb = sm + (kt & 1) * STAGE;
        const uint32_t* Bsb = sm + 2 * STAGE + (kt & 1) * STAGE;

#pragma unroll
        for (int ks = 0; ks < 4; ks++) {
            uint32_t af[4][4], bf[4][2];
#pragma unroll
            for (int mt = 0; mt < 4; mt++) {
                const uint32_t* ap = Asb + (warp_m + mt * 16 + g) * SROW + ks * 8 + t;
                af[mt][0] = ap[0];
                af[mt][1] = ap[8 * SROW];
                af[mt][2] = ap[4];
                af[mt][3] = ap[8 * SROW + 4];
            }
#pragma unroll
            for (int nt = 0; nt < 4; nt++) {
                const uint32_t* bp = Bsb + (warp_n + nt * 8 + g) * SROW + ks * 8 + t;
                bf[nt][0] = bp[0];
                bf[nt][1] = bp[4];
            }
#pragma unroll
            for (int mt = 0; mt < 4; mt++)
#pragma unroll
                for (int nt = 0; nt < 4; nt++)
                    MMA_TF32(acc[mt][nt][0], acc[mt][nt][1],
                             acc[mt][nt][2], acc[mt][nt][3],
                             af[mt][0], af[mt][1], af[mt][2], af[mt][3],
                             bf[nt][0], bf[nt][1]);
        }

        // store next tile into the other buffer (read last at kt-1; all warps
        // passed the kt-1 barrier, so it is free)
        if (kt + 1 < KT) {
            uint32_t* Asn = sm + ((kt + 1) & 1) * STAGE;
            uint32_t* Bsn = sm + 2 * STAGE + ((kt + 1) & 1) * STAGE;
#pragma unroll
            for (int i = 0; i < 4; i++) {
                uint32_t* ap = Asn + (rbase + 32 * i) * SROW + c4;
                uint32_t* bp = Bsn + (rbase + 32 * i) * SROW + c4;
                ap[0] = cvt_tf32(pa[i].x); ap[1] = cvt_tf32(pa[i].y);
                ap[2] = cvt_tf32(pa[i].z); ap[3] = cvt_tf32(pa[i].w);
                bp[0] = cvt_tf32(pb[i].x); bp[1] = cvt_tf32(pb[i].y);
                bp[2] = cvt_tf32(pb[i].z); bp[3] = cvt_tf32(pb[i].w);
            }
        }
        __syncthreads();
    }

    // epilogue: c0/c1 at (row, 2t/2t+1), c2/c3 at (row+8, ...)
#pragma unroll
    for (int mt = 0; mt < 4; mt++) {
        const int r_lo = row0 + warp_m + mt * 16 + g;
#pragma unroll
        for (int nt = 0; nt < 4; nt++) {
            const int cc = col0 + warp_n + nt * 8 + 2 * t;
            *(float2*)(C + (size_t)r_lo * N + cc) =
                make_float2(acc[mt][nt][0], acc[mt][nt][1]);
            *(float2*)(C + (size_t)(r_lo + 8) * N + cc) =
                make_float2(acc[mt][nt][2], acc[mt][nt][3]);
        }
    }
}

// ---------------------------------------------------------------------------
// Causal flash attention, fp32 (unchanged, verified in Round 1).
// ---------------------------------------------------------------------------
__global__ __launch_bounds__(256, 2)
void attn_fwd(const float* __restrict__ qkv, float* __restrict__ out) {
    __shared__ __align__(16) float Qs[BQ * HD_];
    __shared__ __align__(16) float Ks[BK * HD_];
    __shared__ __align__(16) float Ps[BQ * BK];

    const int bh = blockIdx.y;
    const int b  = bh >> 4;
    const int h  = bh & 15;
    const int q0 = blockIdx.x << 6;

    const int tid = threadIdx.x;
    const int tx  = tid & 15;
    const int ty  = tid >> 4;

    const size_t row_base = (size_t)b * S_LEN;
    const unsigned FULL = 0xffffffffu;

#pragma unroll
    for (int i = tid; i < BQ * 16; i += 256) {
        int r = i >> 4, v = i & 15;
        float4 q = *(const float4*)(qkv + (row_base + q0 + r) * QKV_LD + h * HD_ + v * 4);
        ((float4*)Qs)[r * 16 + (v ^ (r & 7))] = q;
    }

    float m[4], l[4], o[4][4];
#pragma unroll
    for (int i = 0; i < 4; i++) {
        m[i] = -1e30f; l[i] = 0.f;
#pragma unroll
        for (int j = 0; j < 4; j++) o[i][j] = 0.f;
    }

    const int qb[4] = {(ty * 4 + 0) * 16, (ty * 4 + 1) * 16,
                       (ty * 4 + 2) * 16, (ty * 4 + 3) * 16};
    const int qx[4] = {(ty * 4 + 0) & 7, (ty * 4 + 1) & 7,
                       (ty * 4 + 2) & 7, (ty * 4 + 3) & 7};
    const int kb[4] = {(tx * 4 + 0) * 16, (tx * 4 + 1) * 16,
                       (tx * 4 + 2) * 16, (tx * 4 + 3) * 16};
    const int kx[4] = {(tx * 4 + 0) & 7, (tx * 4 + 1) & 7,
                       (tx * 4 + 2) & 7, (tx * 4 + 3) & 7};

    for (int k0 = 0; k0 < q0 + BQ; k0 += BK) {
#pragma unroll
        for (int i = tid; i < BK * 16; i += 256) {
            int r = i >> 4, v = i & 15;
            float4 kx4 = *(const float4*)(qkv + (row_base + k0 + r) * QKV_LD +
                                          D_DIM + h * HD_ + v * 4);
            ((float4*)Ks)[r * 16 + (v ^ (r & 7))] = kx4;
        }
        __syncthreads();

        float acc[4][4];
#pragma unroll
        for (int i = 0; i < 4; i++)
#pragma unroll
            for (int j = 0; j < 4; j++) acc[i][j] = 0.f;

#pragma unroll
        for (int v = 0; v < 16; v++) {
            float4 qv[4], kv[4];
#pragma unroll
            for (int i = 0; i < 4; i++)
                qv[i] = ((const float4*)Qs)[qb[i] + (v ^ qx[i])];
#pragma unroll
            for (int j = 0; j < 4; j++)
                kv[j] = ((const float4*)Ks)[kb[j] + (v ^ kx[j])];
#pragma unroll
            for (int i = 0; i < 4; i++)
#pragma unroll
                for (int j = 0; j < 4; j++)
                    acc[i][j] += qv[i].x * kv[j].x + qv[i].y * kv[j].y +
                                 qv[i].z * kv[j].z + qv[i].w * kv[j].w;
        }

        const bool diag = (k0 == q0);
#pragma unroll
        for (int i = 0; i < 4; i++)
#pragma unroll
            for (int j = 0; j < 4; j++) {
                acc[i][j] *= 0.125f;
                if (diag && (tx * 4 + j) > (ty * 4 + i)) acc[i][j] = -1e30f;
            }

#pragma unroll
        for (int i = 0; i < 4; i++) {
            float mt = fmaxf(fmaxf(acc[i][0], acc[i][1]),
                             fmaxf(acc[i][2], acc[i][3]));
            mt = fmaxf(mt, __shfl_xor_sync(FULL, mt, 1));
            mt = fmaxf(mt, __shfl_xor_sync(FULL, mt, 2));
            mt = fmaxf(mt, __shfl_xor_sync(FULL, mt, 4));
            mt = fmaxf(mt, __shfl_xor_sync(FULL, mt, 8));
            float mn   = fmaxf(m[i], mt);
            float corr = __expf(m[i] - mn);
            float sum  = 0.f;
#pragma unroll
            for (int j = 0; j < 4; j++) {
                float p = __expf(acc[i][j] - mn);
                acc[i][j] = p;
                sum += p;
            }
            sum += __shfl_xor_sync(FULL, sum, 1);
            sum += __shfl_xor_sync(FULL, sum, 2);
            sum += __shfl_xor_sync(FULL, sum, 4);
            sum += __shfl_xor_sync(FULL, sum, 8);
            l[i] = l[i] * corr + sum;
            m[i] = mn;
#pragma unroll
            for (int j = 0; j < 4; j++) o[i][j] *= corr;
        }

#pragma unroll
        for (int i = 0; i < 4; i++)
            ((float4*)Ps)[(ty * 4 + i) * 16 + tx] =
                make_float4(acc[i][0], acc[i][1], acc[i][2], acc[i][3]);

        __syncthreads();

#pragma unroll 8
        for (int kk = 0; kk < BK; kk++) {
            float4 vv = *(const float4*)(qkv + (row_base + k0 + kk) * QKV_LD +
                                         2 * D_DIM + h * HD_ + tx * 4);
            float p[4];
#pragma unroll
            for (int i = 0; i < 4; i++) p[i] = Ps[(ty * 4 + i) * 64 + kk];
#pragma unroll
            for (int i = 0; i < 4; i++) {
                o[i][0] += p[i] * vv.x;
                o[i][1] += p[i] * vv.y;
                o[i][2] += p[i] * vv.z;
                o[i][3] += p[i] * vv.w;
            }
        }
    }

#pragma unroll
    for (int i = 0; i < 4; i++) {
        float inv = 1.0f / l[i];
        float4 res = make_float4(o[i][0] * inv, o[i][1] * inv,
                                 o[i][2] * inv, o[i][3] * inv);
        *(float4*)(out + (row_base + q0 + ty * 4 + i) * D_DIM + h * HD_ + tx * 4) = res;
    }
}

// ---------------------------------------------------------------------------
extern "C" void kernel_launch(void* const* d_in, const int* in_sizes, int n_in,
                              void* d_out, int out_size) {
    const float* x      = (const float*)d_in[0];  // [B, S, D]
    const float* w_attn = (const float*)d_in[1];  // [3D, D]
    const float* w_proj = (const float*)d_in[2];  // [D, D]
    float* outp         = (float*)d_out;          // [B, S, D]

    void* p_qkv = nullptr;
    void* p_att = nullptr;
    cudaGetSymbolAddress(&p_qkv, g_qkv);
    cudaGetSymbolAddress(&p_att, g_att);
    float* qkv = (float*)p_qkv;
    float* att = (float*)p_att;

    const int M = B_SZ * S_LEN;  // 8192

    cudaFuncSetAttribute(sgemm_mma, cudaFuncAttributeMaxDynamicSharedMemorySize,
                         GSMEM_BYTES);

    // 1) QKV = X @ W_attn^T : [8192,1024] x [3072,1024]^T  (tf32 mma.sync)
    sgemm_mma<<<dim3(QKV_LD / 128, M / 128), 256, GSMEM_BYTES>>>(
        x, w_attn, qkv, M, QKV_LD, D_DIM);

    // 2) causal attention -> att [8192, 1024]
    attn_fwd<<<dim3(S_LEN / BQ, B_SZ * NH), 256>>>(qkv, att);

    // 3) out = att @ W_proj^T : [8192,1024] x [1024,1024]^T  (tf32 mma.sync)
    sgemm_mma<<<dim3(D_DIM / 128, M / 128), 256, GSMEM_BYTES>>>(
        att, w_proj, outp, M, D_DIM, D_DIM);
}

// round 4
// speedup vs baseline: 3.3474x; 2.2664x over previous
#include <cuda_runtime.h>
#include <math.h>
#include <cstdint>

#define B_SZ   4
#define S_LEN  2048
#define D_DIM  1024
#define NH     16
#define HD_    64
#define QKV_LD 3072

// Scratch (no runtime allocation allowed).
__device__ float g_qkv[(size_t)B_SZ * S_LEN * QKV_LD]; // [B*S, 3D]
__device__ float g_att[(size_t)B_SZ * S_LEN * D_DIM];  // [B*S, D] attention out

// ---------------------------------------------------------------------------
// tf32 helpers (target-neutral mma.sync path; works on plain sm_103 target)
// ---------------------------------------------------------------------------
__device__ __forceinline__ uint32_t cvt_tf32(float f) {
    uint32_t r;
    asm("cvt.rna.tf32.f32 %0, %1;" : "=r"(r) : "f"(f));
    return r;
}

#define MMA_TF32(d0, d1, d2, d3, a0, a1, a2, a3, b0, b1)                      \
    asm volatile(                                                             \
        "mma.sync.aligned.m16n8k8.row.col.f32.tf32.tf32.f32 "                 \
        "{%0,%1,%2,%3}, {%4,%5,%6,%7}, {%8,%9}, {%0,%1,%2,%3};"               \
        : "+f"(d0), "+f"(d1), "+f"(d2), "+f"(d3)                              \
        : "r"(a0), "r"(a1), "r"(a2), "r"(a3), "r"(b0), "r"(b1))

// ---------------------------------------------------------------------------
// Tensor-core SGEMM (tf32 mma.sync, NT): C[M,N] = A[M,K] * B[N,K]^T.
// (verified in Round 3, unchanged)
// ---------------------------------------------------------------------------
#define SROW 36
#define STAGE (128 * SROW)
#define GSMEM_BYTES (4 * STAGE * 4)

__global__ __launch_bounds__(256)
void sgemm_mma(const float* __restrict__ A, const float* __restrict__ B,
               float* __restrict__ C, int M, int N, int K) {
    extern __shared__ __align__(16) uint32_t sm[];
    const int tid  = threadIdx.x;
    const int wid  = tid >> 5;
    const int lane = tid & 31;
    const int g    = lane >> 2;
    const int t    = lane & 3;
    const int row0 = blockIdx.y << 7;
    const int col0 = blockIdx.x << 7;
    const int warp_m = (wid >> 2) * 64;
    const int warp_n = (wid & 3) * 32;
    const int rbase = tid >> 3;
    const int c4    = (tid & 7) * 4;

    float acc[4][4][4];
#pragma unroll
    for (int i = 0; i < 4; i++)
#pragma unroll
        for (int j = 0; j < 4; j++)
#pragma unroll
            for (int k = 0; k < 4; k++) acc[i][j][k] = 0.f;

    const int KT = K >> 5;
    float4 pa[4], pb[4];

#pragma unroll
    for (int i = 0; i < 4; i++) {
        pa[i] = *(const float4*)(A + (size_t)(row0 + rbase + 32 * i) * K + c4);
        pb[i] = *(const float4*)(B + (size_t)(col0 + rbase + 32 * i) * K + c4);
    }
#pragma unroll
    for (int i = 0; i < 4; i++) {
        uint32_t* ap = sm + (rbase + 32 * i) * SROW + c4;
        uint32_t* bp = sm + 2 * STAGE + (rbase + 32 * i) * SROW + c4;
        ap[0] = cvt_tf32(pa[i].x); ap[1] = cvt_tf32(pa[i].y);
        ap[2] = cvt_tf32(pa[i].z); ap[3] = cvt_tf32(pa[i].w);
        bp[0] = cvt_tf32(pb[i].x); bp[1] = cvt_tf32(pb[i].y);
        bp[2] = cvt_tf32(pb[i].z); bp[3] = cvt_tf32(pb[i].w);
    }
    __syncthreads();

    for (int kt = 0; kt < KT; kt++) {
        if (kt + 1 < KT) {
            const int kb = (kt + 1) << 5;
#pragma unroll
            for (int i = 0; i < 4; i++) {
                pa[i] = *(const float4*)(A + (size_t)(row0 + rbase + 32 * i) * K + kb + c4);
                pb[i] = *(const float4*)(B + (size_t)(col0 + rbase + 32 * i) * K + kb + c4);
            }
        }

        const uint32_t* Asb = sm + (kt & 1) * STAGE;
        const uint32_t* Bsb = sm + 2 * STAGE + (kt & 1) * STAGE;

#pragma unroll
        for (int ks = 0; ks < 4; ks++) {
            uint32_t af[4][4], bf[4][2];
#pragma unroll
            for (int mt = 0; mt < 4; mt++) {
                const uint32_t* ap = Asb + (warp_m + mt * 16 + g) * SROW + ks * 8 + t;
                af[mt][0] = ap[0];
                af[mt][1] = ap[8 * SROW];
                af[mt][2] = ap[4];
                af[mt][3] = ap[8 * SROW + 4];
            }
#pragma unroll
            for (int nt = 0; nt < 4; nt++) {
                const uint32_t* bp = Bsb + (warp_n + nt * 8 + g) * SROW + ks * 8 + t;
                bf[nt][0] = bp[0];
                bf[nt][1] = bp[4];
            }
#pragma unroll
            for (int mt = 0; mt < 4; mt++)
#pragma unroll
                for (int nt = 0; nt < 4; nt++)
                    MMA_TF32(acc[mt][nt][0], acc[mt][nt][1],
                             acc[mt][nt][2], acc[mt][nt][3],
                             af[mt][0], af[mt][1], af[mt][2], af[mt][3],
                             bf[nt][0], bf[nt][1]);
        }

        if (kt + 1 < KT) {
            uint32_t* Asn = sm + ((kt + 1) & 1) * STAGE;
            uint32_t* Bsn = sm + 2 * STAGE + ((kt + 1) & 1) * STAGE;
#pragma unroll
            for (int i = 0; i < 4; i++) {
                uint32_t* ap = Asn + (rbase + 32 * i) * SROW + c4;
                uint32_t* bp = Bsn + (rbase + 32 * i) * SROW + c4;
                ap[0] = cvt_tf32(pa[i].x); ap[1] = cvt_tf32(pa[i].y);
                ap[2] = cvt_tf32(pa[i].z); ap[3] = cvt_tf32(pa[i].w);
                bp[0] = cvt_tf32(pb[i].x); bp[1] = cvt_tf32(pb[i].y);
                bp[2] = cvt_tf32(pb[i].z); bp[3] = cvt_tf32(pb[i].w);
            }
        }
        __syncthreads();
    }

#pragma unroll
    for (int mt = 0; mt < 4; mt++) {
        const int r_lo = row0 + warp_m + mt * 16 + g;
#pragma unroll
        for (int nt = 0; nt < 4; nt++) {
            const int cc = col0 + warp_n + nt * 8 + 2 * t;
            *(float2*)(C + (size_t)r_lo * N + cc) =
                make_float2(acc[mt][nt][0], acc[mt][nt][1]);
            *(float2*)(C + (size_t)(r_lo + 8) * N + cc) =
                make_float2(acc[mt][nt][2], acc[mt][nt][3]);
        }
    }
}

// ---------------------------------------------------------------------------
// Causal flash attention, tf32 mma.sync.
// grid (S/128, B*H), 256 threads (8 warps). Warp w owns query rows
// [w*16, w*16+16). Q fragments register-resident. Per 64-key tile: K,V ->
// smem (tf32, stride 68 = conflict-free frags), scores = 8x8 m16n8k8 MMAs,
// online softmax in accumulator layout (quad shfl reductions), P via
// warp-private smem, PV = 8x8 MMAs.
// Smem: Ks[64*68] | Vs[64*68] | Ps[8 warps * 16*68]  (Ps doubles as Q staging)
// ---------------------------------------------------------------------------
#define ATT_SROW 68
#define ATT_VS   (64 * ATT_SROW)
#define ATT_PS   (2 * 64 * ATT_SROW)
#define ATT_SMEM_BYTES ((2 * 64 * ATT_SROW + 128 * ATT_SROW) * 4)

__global__ __launch_bounds__(256)
void attn_mma(const float* __restrict__ qkv, float* __restrict__ out) {
    extern __shared__ __align__(16) uint32_t sm2[];

    const int bh = blockIdx.y;
    const int b  = bh >> 4;
    const int h  = bh & 15;
    const int q0 = blockIdx.x << 7;

    const int tid  = threadIdx.x;
    const int wid  = tid >> 5;
    const int lane = tid & 31;
    const int g    = lane >> 2;
    const int t    = lane & 3;

    const size_t row_base = (size_t)b * S_LEN;

    // ---- stage Q tile (tf32) into Ps region, then lift fragments ----
#pragma unroll
    for (int i = 0; i < 8; i++) {
        const int idx = tid + i * 256;       // 0..2047
        const int r   = idx >> 4;            // 0..127
        const int c4  = (idx & 15) * 4;
        float4 v = *(const float4*)(qkv + (row_base + q0 + r) * QKV_LD + h * HD_ + c4);
        uint32_t* p = sm2 + ATT_PS + r * ATT_SROW + c4;
        p[0] = cvt_tf32(v.x); p[1] = cvt_tf32(v.y);
        p[2] = cvt_tf32(v.z); p[3] = cvt_tf32(v.w);
    }
    __syncthreads();

    uint32_t qf[8][4];
    {
        const uint32_t* qs = sm2 + ATT_PS + (wid * 16 + g) * ATT_SROW;
#pragma unroll
        for (int ks = 0; ks < 8; ks++) {
            const uint32_t* p = qs + ks * 8 + t;
            qf[ks][0] = p[0];
            qf[ks][1] = p[8 * ATT_SROW];
            qf[ks][2] = p[4];
            qf[ks][3] = p[8 * ATT_SROW + 4];
        }
    }

    float m0 = -1e30f, m1 = -1e30f, l0 = 0.f, l1 = 0.f;
    float o[8][4];
#pragma unroll
    for (int nt = 0; nt < 8; nt++)
#pragma unroll
        for (int j = 0; j < 4; j++) o[nt][j] = 0.f;

    uint32_t* const pw = sm2 + ATT_PS + wid * (16 * ATT_SROW);
    const int myrowmax = q0 + wid * 16 + 15;
    const int nkt = (q0 >> 6) + 2;
    const unsigned FULL = 0xffffffffu;

    for (int kt = 0; kt < nkt; kt++) {
        const int k0 = kt << 6;

        // ---- load K,V tiles (tf32) ----
        {
            const int r  = tid >> 2;          // 0..63
            const int cb = (tid & 3) * 16;
            const float* kg = qkv + (row_base + k0 + r) * QKV_LD + D_DIM + h * HD_ + cb;
            uint32_t* kp = sm2 + r * ATT_SROW + cb;
            uint32_t* vp = sm2 + ATT_VS + r * ATT_SROW + cb;
#pragma unroll
            for (int i = 0; i < 4; i++) {
                float4 kv = *(const float4*)(kg + i * 4);
                float4 vv = *(const float4*)(kg + D_DIM + i * 4);
                kp[i * 4 + 0] = cvt_tf32(kv.x); kp[i * 4 + 1] = cvt_tf32(kv.y);
                kp[i * 4 + 2] = cvt_tf32(kv.z); kp[i * 4 + 3] = cvt_tf32(kv.w);
                vp[i * 4 + 0] = cvt_tf32(vv.x); vp[i * 4 + 1] = cvt_tf32(vv.y);
                vp[i * 4 + 2] = cvt_tf32(vv.z); vp[i * 4 + 3] = cvt_tf32(vv.w);
            }
        }
        __syncthreads();

        if (k0 <= myrowmax) {   // warp-uniform: tile not fully masked
            // ---- scores S = Q K^T ----
            float acc[8][4];
#pragma unroll
            for (int nt = 0; nt < 8; nt++)
#pragma unroll
                for (int j = 0; j < 4; j++) acc[nt][j] = 0.f;

#pragma unroll
            for (int ks = 0; ks < 8; ks++) {
                uint32_t bf[8][2];
#pragma unroll
                for (int nt = 0; nt < 8; nt++) {
                    const uint32_t* bp = sm2 + (nt * 8 + g) * ATT_SROW + ks * 8 + t;
                    bf[nt][0] = bp[0];
                    bf[nt][1] = bp[4];
                }
#pragma unroll
                for (int nt = 0; nt < 8; nt++)
                    MMA_TF32(acc[nt][0], acc[nt][1], acc[nt][2], acc[nt][3],
                             qf[ks][0], qf[ks][1], qf[ks][2], qf[ks][3],
                             bf[nt][0], bf[nt][1]);
            }

            // ---- scale + causal mask ----
            const int r0 = q0 + wid * 16 + g;
            const int r1 = r0 + 8;
            const bool needmask = (k0 + 63 > q0 + wid * 16);
#pragma unroll
            for (int nt = 0; nt < 8; nt++) {
                const int col = k0 + nt * 8 + 2 * t;
                acc[nt][0] *= 0.125f; acc[nt][1] *= 0.125f;
                acc[nt][2] *= 0.125f; acc[nt][3] *= 0.125f;
                if (needmask) {
                    if (col > r0)     acc[nt][0] = -1e30f;
                    if (col + 1 > r0) acc[nt][1] = -1e30f;
                    if (col > r1)     acc[nt][2] = -1e30f;
                    if (col + 1 > r1) acc[nt][3] = -1e30f;
                }
            }

            // ---- online softmax (rows g and g+8; reduce over quad lanes) ----
            float mt0 = -1e30f, mt1 = -1e30f;
#pragma unroll
            for (int nt = 0; nt < 8; nt++) {
                mt0 = fmaxf(mt0, fmaxf(acc[nt][0], acc[nt][1]));
                mt1 = fmaxf(mt1, fmaxf(acc[nt][2], acc[nt][3]));
            }
            mt0 = fmaxf(mt0, __shfl_xor_sync(FULL, mt0, 1));
            mt0 = fmaxf(mt0, __shfl_xor_sync(FULL, mt0, 2));
            mt1 = fmaxf(mt1, __shfl_xor_sync(FULL, mt1, 1));
            mt1 = fmaxf(mt1, __shfl_xor_sync(FULL, mt1, 2));

            const float mn0 = fmaxf(m0, mt0);
            const float mn1 = fmaxf(m1, mt1);
            const float c0 = __expf(m0 - mn0);
            const float c1 = __expf(m1 - mn1);
            float s0 = 0.f, s1 = 0.f;
#pragma unroll
            for (int nt = 0; nt < 8; nt++) {
                acc[nt][0] = __expf(acc[nt][0] - mn0); s0 += acc[nt][0];
                acc[nt][1] = __expf(acc[nt][1] - mn0); s0 += acc[nt][1];
                acc[nt][2] = __expf(acc[nt][2] - mn1); s1 += acc[nt][2];
                acc[nt][3] = __expf(acc[nt][3] - mn1); s1 += acc[nt][3];
            }
            s0 += __shfl_xor_sync(FULL, s0, 1);
            s0 += __shfl_xor_sync(FULL, s0, 2);
            s1 += __shfl_xor_sync(FULL, s1, 1);
            s1 += __shfl_xor_sync(FULL, s1, 2);
            l0 = l0 * c0 + s0; m0 = mn0;
            l1 = l1 * c1 + s1; m1 = mn1;
#pragma unroll
            for (int nt = 0; nt < 8; nt++) {
                o[nt][0] *= c0; o[nt][1] *= c0;
                o[nt][2] *= c1; o[nt][3] *= c1;
            }

            // ---- P -> warp-private smem (tf32) ----
#pragma unroll
            for (int nt = 0; nt < 8; nt++) {
                uint32_t* p0 = pw + g * ATT_SROW + nt * 8 + 2 * t;
                uint32_t* p1 = pw + (g + 8) * ATT_SROW + nt * 8 + 2 * t;
                p0[0] = cvt_tf32(acc[nt][0]); p0[1] = cvt_tf32(acc[nt][1]);
                p1[0] = cvt_tf32(acc[nt][2]); p1[1] = cvt_tf32(acc[nt][3]);
            }
            __syncwarp();

            // ---- O += P V ----
#pragma unroll
            for (int ks = 0; ks < 8; ks++) {
                const uint32_t* pa = pw + g * ATT_SROW + ks * 8 + t;
                const uint32_t a0 = pa[0];
                const uint32_t a1 = pa[8 * ATT_SROW];
                const uint32_t a2 = pa[4];
                const uint32_t a3 = pa[8 * ATT_SROW + 4];
#pragma unroll
                for (int nt = 0; nt < 8; nt++) {
                    const uint32_t* vb = sm2 + ATT_VS + (ks * 8 + t) * ATT_SROW + nt * 8 + g;
                    const uint32_t b0 = vb[0];
                    const uint32_t b1 = vb[4 * ATT_SROW];
                    MMA_TF32(o[nt][0], o[nt][1], o[nt][2], o[nt][3],
                             a0, a1, a2, a3, b0, b1);
                }
            }
        }
        __syncthreads();
    }

    // ---- epilogue ----
    const float i0 = 1.0f / l0;
    const float i1 = 1.0f / l1;
    const size_t r0 = row_base + q0 + wid * 16 + g;
#pragma unroll
    for (int nt = 0; nt < 8; nt++) {
        const int col = h * HD_ + nt * 8 + 2 * t;
        *(float2*)(out + r0 * D_DIM + col) =
            make_float2(o[nt][0] * i0, o[nt][1] * i0);
        *(float2*)(out + (r0 + 8) * D_DIM + col) =
            make_float2(o[nt][2] * i1, o[nt][3] * i1);
    }
}

// ---------------------------------------------------------------------------
extern "C" void kernel_launch(void* const* d_in, const int* in_sizes, int n_in,
                              void* d_out, int out_size) {
    const float* x      = (const float*)d_in[0];  // [B, S, D]
    const float* w_attn = (const float*)d_in[1];  // [3D, D]
    const float* w_proj = (const float*)d_in[2];  // [D, D]
    float* outp         = (float*)d_out;          // [B, S, D]

    void* p_qkv = nullptr;
    void* p_att = nullptr;
    cudaGetSymbolAddress(&p_qkv, g_qkv);
    cudaGetSymbolAddress(&p_att, g_att);
    float* qkv = (float*)p_qkv;
    float* att = (float*)p_att;

    const int M = B_SZ * S_LEN;  // 8192

    cudaFuncSetAttribute(sgemm_mma, cudaFuncAttributeMaxDynamicSharedMemorySize,
                         GSMEM_BYTES);
    cudaFuncSetAttribute(attn_mma, cudaFuncAttributeMaxDynamicSharedMemorySize,
                         ATT_SMEM_BYTES);

    // 1) QKV = X @ W_attn^T  (tf32 mma.sync)
    sgemm_mma<<<dim3(QKV_LD / 128, M / 128), 256, GSMEM_BYTES>>>(
        x, w_attn, qkv, M, QKV_LD, D_DIM);

    // 2) causal attention -> att [8192, 1024]  (tf32 mma.sync)
    attn_mma<<<dim3(S_LEN / 128, B_SZ * NH), 256, ATT_SMEM_BYTES>>>(qkv, att);

    // 3) out = att @ W_proj^T  (tf32 mma.sync)
    sgemm_mma<<<dim3(D_DIM / 128, M / 128), 256, GSMEM_BYTES>>>(
        att, w_proj, outp, M, D_DIM, D_DIM);
}

// round 5
// speedup vs baseline: 3.5474x; 1.0597x over previous
#include <cuda_runtime.h>
#include <math.h>
#include <cstdint>

#define B_SZ   4
#define S_LEN  2048
#define D_DIM  1024
#define NH     16
#define HD_    64
#define QKV_LD 3072

// Scratch (no runtime allocation allowed).
__device__ float g_qkv[(size_t)B_SZ * S_LEN * QKV_LD]; // [B*S, 3D]
__device__ float g_att[(size_t)B_SZ * S_LEN * D_DIM];  // [B*S, D] attention out

// ---------------------------------------------------------------------------
// tf32 helpers (target-neutral mma.sync path; works on plain sm_103 target)
// ---------------------------------------------------------------------------
__device__ __forceinline__ uint32_t cvt_tf32(float f) {
    uint32_t r;
    asm("cvt.rna.tf32.f32 %0, %1;" : "=r"(r) : "f"(f));
    return r;
}

#define MMA_TF32(d0, d1, d2, d3, a0, a1, a2, a3, b0, b1)                      \
    asm volatile(                                                             \
        "mma.sync.aligned.m16n8k8.row.col.f32.tf32.tf32.f32 "                 \
        "{%0,%1,%2,%3}, {%4,%5,%6,%7}, {%8,%9}, {%0,%1,%2,%3};"               \
        : "+f"(d0), "+f"(d1), "+f"(d2), "+f"(d3)                              \
        : "r"(a0), "r"(a1), "r"(a2), "r"(a3), "r"(b0), "r"(b1))

// ---------------------------------------------------------------------------
// Tensor-core SGEMM (tf32 mma.sync, NT): C[M,N] = A[M,K] * B[N,K]^T.
// Row-major; M%128==0, N%256==0, K%32==0.
// 256 threads (8 warps as 2x4), CTA tile 128x256, warp tile 64x64
// (4x8 m16n8k8 accumulators). Double-buffered smem (K-tile 32), one
// __syncthreads per tile, register-prefetch of the next global tile.
// Smem row stride 36 floats: 16B-aligned rows + conflict-free fragment reads.
// ---------------------------------------------------------------------------
#define SROW 36
#define ASTG (128 * SROW)
#define BSTG (256 * SROW)
#define GSMEM_BYTES ((2 * ASTG + 2 * BSTG) * 4)   // 110592 B

__global__ __launch_bounds__(256)
void sgemm_mma(const float* __restrict__ A, const float* __restrict__ B,
               float* __restrict__ C, int M, int N, int K) {
    extern __shared__ __align__(16) uint32_t sm[];
    // layout: A0 | A1 | B0 | B1
    const int tid  = threadIdx.x;
    const int wid  = tid >> 5;
    const int lane = tid & 31;
    const int g    = lane >> 2;       // 0..7
    const int t    = lane & 3;        // 0..3
    const int row0 = blockIdx.y << 7;
    const int col0 = blockIdx.x << 8;
    const int warp_m = (wid & 1) * 64;
    const int warp_n = (wid >> 1) * 64;

    const int rbase = tid >> 3;       // 0..31
    const int c4    = (tid & 7) * 4;  // 0,4,..28

    float acc[4][8][4];
#pragma unroll
    for (int i = 0; i < 4; i++)
#pragma unroll
        for (int j = 0; j < 8; j++)
#pragma unroll
            for (int k = 0; k < 4; k++) acc[i][j][k] = 0.f;

    const int KT = K >> 5;
    float4 pa[4], pb[8];

    const float* Abase = A + (size_t)(row0 + rbase) * K + c4;
    const float* Bbase = B + (size_t)(col0 + rbase) * K + c4;

    // prologue: global prefetch of k-tile 0
#pragma unroll
    for (int i = 0; i < 4; i++)
        pa[i] = *(const float4*)(Abase + (size_t)(32 * i) * K);
#pragma unroll
    for (int i = 0; i < 8; i++)
        pb[i] = *(const float4*)(Bbase + (size_t)(32 * i) * K);

    // store stage 0 (with tf32 round)
#pragma unroll
    for (int i = 0; i < 4; i++) {
        uint32_t* ap = sm + (rbase + 32 * i) * SROW + c4;
        ap[0] = cvt_tf32(pa[i].x); ap[1] = cvt_tf32(pa[i].y);
        ap[2] = cvt_tf32(pa[i].z); ap[3] = cvt_tf32(pa[i].w);
    }
#pragma unroll
    for (int i = 0; i < 8; i++) {
        uint32_t* bp = sm + 2 * ASTG + (rbase + 32 * i) * SROW + c4;
        bp[0] = cvt_tf32(pb[i].x); bp[1] = cvt_tf32(pb[i].y);
        bp[2] = cvt_tf32(pb[i].z); bp[3] = cvt_tf32(pb[i].w);
    }
    __syncthreads();

    for (int kt = 0; kt < KT; kt++) {
        if (kt + 1 < KT) {
            const int kb = (kt + 1) << 5;
#pragma unroll
            for (int i = 0; i < 4; i++)
                pa[i] = *(const float4*)(Abase + (size_t)(32 * i) * K + kb);
#pragma unroll
            for (int i = 0; i < 8; i++)
                pb[i] = *(const float4*)(Bbase + (size_t)(32 * i) * K + kb);
        }

        const uint32_t* Asb = sm + (kt & 1) * ASTG;
        const uint32_t* Bsb = sm + 2 * ASTG + (kt & 1) * BSTG;

#pragma unroll
        for (int ks = 0; ks < 4; ks++) {
            uint32_t af[4][4], bf[8][2];
#pragma unroll
            for (int mt = 0; mt < 4; mt++) {
                const uint32_t* ap = Asb + (warp_m + mt * 16 + g) * SROW + ks * 8 + t;
                af[mt][0] = ap[0];
                af[mt][1] = ap[8 * SROW];
                af[mt][2] = ap[4];
                af[mt][3] = ap[8 * SROW + 4];
            }
#pragma unroll
            for (int nt = 0; nt < 8; nt++) {
                const uint32_t* bp = Bsb + (warp_n + nt * 8 + g) * SROW + ks * 8 + t;
                bf[nt][0] = bp[0];
                bf[nt][1] = bp[4];
            }
#pragma unroll
            for (int mt = 0; mt < 4; mt++)
#pragma unroll
                for (int nt = 0; nt < 8; nt++)
                    MMA_TF32(acc[mt][nt][0], acc[mt][nt][1],
                             acc[mt][nt][2], acc[mt][nt][3],
                             af[mt][0], af[mt][1], af[mt][2], af[mt][3],
                             bf[nt][0], bf[nt][1]);
        }

        if (kt + 1 < KT) {
            uint32_t* Asn = sm + ((kt + 1) & 1) * ASTG;
            uint32_t* Bsn = sm + 2 * ASTG + ((kt + 1) & 1) * BSTG;
#pragma unroll
            for (int i = 0; i < 4; i++) {
                uint32_t* ap = Asn + (rbase + 32 * i) * SROW + c4;
                ap[0] = cvt_tf32(pa[i].x); ap[1] = cvt_tf32(pa[i].y);
                ap[2] = cvt_tf32(pa[i].z); ap[3] = cvt_tf32(pa[i].w);
            }
#pragma unroll
            for (int i = 0; i < 8; i++) {
                uint32_t* bp = Bsn + (rbase + 32 * i) * SROW + c4;
                bp[0] = cvt_tf32(pb[i].x); bp[1] = cvt_tf32(pb[i].y);
                bp[2] = cvt_tf32(pb[i].z); bp[3] = cvt_tf32(pb[i].w);
            }
        }
        __syncthreads();
    }

    // epilogue
#pragma unroll
    for (int mt = 0; mt < 4; mt++) {
        const int r_lo = row0 + warp_m + mt * 16 + g;
#pragma unroll
        for (int nt = 0; nt < 8; nt++) {
            const int cc = col0 + warp_n + nt * 8 + 2 * t;
            *(float2*)(C + (size_t)r_lo * N + cc) =
                make_float2(acc[mt][nt][0], acc[mt][nt][1]);
            *(float2*)(C + (size_t)(r_lo + 8) * N + cc) =
                make_float2(acc[mt][nt][2], acc[mt][nt][3]);
        }
    }
}

// ---------------------------------------------------------------------------
// Causal flash attention, tf32 mma.sync (verified in Round 4).
// Only change: q-tile order reversed so heavy (long-history) CTAs launch
// first, shrinking the final-wave tail of the causal triangle.
// ---------------------------------------------------------------------------
#define ATT_SROW 68
#define ATT_VS   (64 * ATT_SROW)
#define ATT_PS   (2 * 64 * ATT_SROW)
#define ATT_SMEM_BYTES ((2 * 64 * ATT_SROW + 128 * ATT_SROW) * 4)

__global__ __launch_bounds__(256)
void attn_mma(const float* __restrict__ qkv, float* __restrict__ out) {
    extern __shared__ __align__(16) uint32_t sm2[];

    const int bh = blockIdx.y;
    const int b  = bh >> 4;
    const int h  = bh & 15;
    const int q0 = (int)(gridDim.x - 1 - blockIdx.x) << 7;

    const int tid  = threadIdx.x;
    const int wid  = tid >> 5;
    const int lane = tid & 31;
    const int g    = lane >> 2;
    const int t    = lane & 3;

    const size_t row_base = (size_t)b * S_LEN;

    // ---- stage Q tile (tf32) into Ps region, then lift fragments ----
#pragma unroll
    for (int i = 0; i < 8; i++) {
        const int idx = tid + i * 256;
        const int r   = idx >> 4;
        const int c4  = (idx & 15) * 4;
        float4 v = *(const float4*)(qkv + (row_base + q0 + r) * QKV_LD + h * HD_ + c4);
        uint32_t* p = sm2 + ATT_PS + r * ATT_SROW + c4;
        p[0] = cvt_tf32(v.x); p[1] = cvt_tf32(v.y);
        p[2] = cvt_tf32(v.z); p[3] = cvt_tf32(v.w);
    }
    __syncthreads();

    uint32_t qf[8][4];
    {
        const uint32_t* qs = sm2 + ATT_PS + (wid * 16 + g) * ATT_SROW;
#pragma unroll
        for (int ks = 0; ks < 8; ks++) {
            const uint32_t* p = qs + ks * 8 + t;
            qf[ks][0] = p[0];
            qf[ks][1] = p[8 * ATT_SROW];
            qf[ks][2] = p[4];
            qf[ks][3] = p[8 * ATT_SROW + 4];
        }
    }

    float m0 = -1e30f, m1 = -1e30f, l0 = 0.f, l1 = 0.f;
    float o[8][4];
#pragma unroll
    for (int nt = 0; nt < 8; nt++)
#pragma unroll
        for (int j = 0; j < 4; j++) o[nt][j] = 0.f;

    uint32_t* const pw = sm2 + ATT_PS + wid * (16 * ATT_SROW);
    const int myrowmax = q0 + wid * 16 + 15;
    const int nkt = (q0 >> 6) + 2;
    const unsigned FULL = 0xffffffffu;

    for (int kt = 0; kt < nkt; kt++) {
        const int k0 = kt << 6;

        // ---- load K,V tiles (tf32) ----
        {
            const int r  = tid >> 2;
            const int cb = (tid & 3) * 16;
            const float* kg = qkv + (row_base + k0 + r) * QKV_LD + D_DIM + h * HD_ + cb;
            uint32_t* kp = sm2 + r * ATT_SROW + cb;
            uint32_t* vp = sm2 + ATT_VS + r * ATT_SROW + cb;
#pragma unroll
            for (int i = 0; i < 4; i++) {
                float4 kv = *(const float4*)(kg + i * 4);
                float4 vv = *(const float4*)(kg + D_DIM + i * 4);
                kp[i * 4 + 0] = cvt_tf32(kv.x); kp[i * 4 + 1] = cvt_tf32(kv.y);
                kp[i * 4 + 2] = cvt_tf32(kv.z); kp[i * 4 + 3] = cvt_tf32(kv.w);
                vp[i * 4 + 0] = cvt_tf32(vv.x); vp[i * 4 + 1] = cvt_tf32(vv.y);
                vp[i * 4 + 2] = cvt_tf32(vv.z); vp[i * 4 + 3] = cvt_tf32(vv.w);
            }
        }
        __syncthreads();

        if (k0 <= myrowmax) {   // warp-uniform: tile not fully masked
            // ---- scores S = Q K^T ----
            float acc[8][4];
#pragma unroll
            for (int nt = 0; nt < 8; nt++)
#pragma unroll
                for (int j = 0; j < 4; j++) acc[nt][j] = 0.f;

#pragma unroll
            for (int ks = 0; ks < 8; ks++) {
                uint32_t bf[8][2];
#pragma unroll
                for (int nt = 0; nt < 8; nt++) {
                    const uint32_t* bp = sm2 + (nt * 8 + g) * ATT_SROW + ks * 8 + t;
                    bf[nt][0] = bp[0];
                    bf[nt][1] = bp[4];
                }
#pragma unroll
                for (int nt = 0; nt < 8; nt++)
                    MMA_TF32(acc[nt][0], acc[nt][1], acc[nt][2], acc[nt][3],
                             qf[ks][0], qf[ks][1], qf[ks][2], qf[ks][3],
                             bf[nt][0], bf[nt][1]);
            }

            // ---- scale + causal mask ----
            const int r0 = q0 + wid * 16 + g;
            const int r1 = r0 + 8;
            const bool needmask = (k0 + 63 > q0 + wid * 16);
#pragma unroll
            for (int nt = 0; nt < 8; nt++) {
                const int col = k0 + nt * 8 + 2 * t;
                acc[nt][0] *= 0.125f; acc[nt][1] *= 0.125f;
                acc[nt][2] *= 0.125f; acc[nt][3] *= 0.125f;
                if (needmask) {
                    if (col > r0)     acc[nt][0] = -1e30f;
                    if (col + 1 > r0) acc[nt][1] = -1e30f;
                    if (col > r1)     acc[nt][2] = -1e30f;
                    if (col + 1 > r1) acc[nt][3] = -1e30f;
                }
            }

            // ---- online softmax (rows g and g+8; reduce over quad lanes) ----
            float mt0 = -1e30f, mt1 = -1e30f;
#pragma unroll
            for (int nt = 0; nt < 8; nt++) {
                mt0 = fmaxf(mt0, fmaxf(acc[nt][0], acc[nt][1]));
                mt1 = fmaxf(mt1, fmaxf(acc[nt][2], acc[nt][3]));
            }
            mt0 = fmaxf(mt0, __shfl_xor_sync(FULL, mt0, 1));
            mt0 = fmaxf(mt0, __shfl_xor_sync(FULL, mt0, 2));
            mt1 = fmaxf(mt1, __shfl_xor_sync(FULL, mt1, 1));
            mt1 = fmaxf(mt1, __shfl_xor_sync(FULL, mt1, 2));

            const float mn0 = fmaxf(m0, mt0);
            const float mn1 = fmaxf(m1, mt1);
            const float c0 = __expf(m0 - mn0);
            const float c1 = __expf(m1 - mn1);
            float s0 = 0.f, s1 = 0.f;
#pragma unroll
            for (int nt = 0; nt < 8; nt++) {
                acc[nt][0] = __expf(acc[nt][0] - mn0); s0 += acc[nt][0];
                acc[nt][1] = __expf(acc[nt][1] - mn0); s0 += acc[nt][1];
                acc[nt][2] = __expf(acc[nt][2] - mn1); s1 += acc[nt][2];
                acc[nt][3] = __expf(acc[nt][3] - mn1); s1 += acc[nt][3];
            }
            s0 += __shfl_xor_sync(FULL, s0, 1);
            s0 += __shfl_xor_sync(FULL, s0, 2);
            s1 += __shfl_xor_sync(FULL, s1, 1);
            s1 += __shfl_xor_sync(FULL, s1, 2);
            l0 = l0 * c0 + s0; m0 = mn0;
            l1 = l1 * c1 + s1; m1 = mn1;
#pragma unroll
            for (int nt = 0; nt < 8; nt++) {
                o[nt][0] *= c0; o[nt][1] *= c0;
                o[nt][2] *= c1; o[nt][3] *= c1;
            }

            // ---- P -> warp-private smem (tf32) ----
#pragma unroll
            for (int nt = 0; nt < 8; nt++) {
                uint32_t* p0 = pw + g * ATT_SROW + nt * 8 + 2 * t;
                uint32_t* p1 = pw + (g + 8) * ATT_SROW + nt * 8 + 2 * t;
                p0[0] = cvt_tf32(acc[nt][0]); p0[1] = cvt_tf32(acc[nt][1]);
                p1[0] = cvt_tf32(acc[nt][2]); p1[1] = cvt_tf32(acc[nt][3]);
            }
            __syncwarp();

            // ---- O += P V ----
#pragma unroll
            for (int ks = 0; ks < 8; ks++) {
                const uint32_t* pa = pw + g * ATT_SROW + ks * 8 + t;
                const uint32_t a0 = pa[0];
                const uint32_t a1 = pa[8 * ATT_SROW];
                const uint32_t a2 = pa[4];
                const uint32_t a3 = pa[8 * ATT_SROW + 4];
#pragma unroll
                for (int nt = 0; nt < 8; nt++) {
                    const uint32_t* vb = sm2 + ATT_VS + (ks * 8 + t) * ATT_SROW + nt * 8 + g;
                    const uint32_t b0 = vb[0];
                    const uint32_t b1 = vb[4 * ATT_SROW];
                    MMA_TF32(o[nt][0], o[nt][1], o[nt][2], o[nt][3],
                             a0, a1, a2, a3, b0, b1);
                }
            }
        }
        __syncthreads();
    }

    // ---- epilogue ----
    const float i0 = 1.0f / l0;
    const float i1 = 1.0f / l1;
    const size_t r0 = row_base + q0 + wid * 16 + g;
#pragma unroll
    for (int nt = 0; nt < 8; nt++) {
        const int col = h * HD_ + nt * 8 + 2 * t;
        *(float2*)(out + r0 * D_DIM + col) =
            make_float2(o[nt][0] * i0, o[nt][1] * i0);
        *(float2*)(out + (r0 + 8) * D_DIM + col) =
            make_float2(o[nt][2] * i1, o[nt][3] * i1);
    }
}

// ---------------------------------------------------------------------------
extern "C" void kernel_launch(void* const* d_in, const int* in_sizes, int n_in,
                              void* d_out, int out_size) {
    const float* x      = (const float*)d_in[0];  // [B, S, D]
    const float* w_attn = (const float*)d_in[1];  // [3D, D]
    const float* w_proj = (const float*)d_in[2];  // [D, D]
    float* outp         = (float*)d_out;          // [B, S, D]

    void* p_qkv = nullptr;
    void* p_att = nullptr;
    cudaGetSymbolAddress(&p_qkv, g_qkv);
    cudaGetSymbolAddress(&p_att, g_att);
    float* qkv = (float*)p_qkv;
    float* att = (float*)p_att;

    const int M = B_SZ * S_LEN;  // 8192

    cudaFuncSetAttribute(sgemm_mma, cudaFuncAttributeMaxDynamicSharedMemorySize,
                         GSMEM_BYTES);
    cudaFuncSetAttribute(attn_mma, cudaFuncAttributeMaxDynamicSharedMemorySize,
                         ATT_SMEM_BYTES);

    // 1) QKV = X @ W_attn^T  (tf32 mma.sync, 128x256 CTA tile)
    sgemm_mma<<<dim3(QKV_LD / 256, M / 128), 256, GSMEM_BYTES>>>(
        x, w_attn, qkv, M, QKV_LD, D_DIM);

    // 2) causal attention -> att [8192, 1024]  (tf32 mma.sync)
    attn_mma<<<dim3(S_LEN / 128, B_SZ * NH), 256, ATT_SMEM_BYTES>>>(qkv, att);

    // 3) out = att @ W_proj^T  (tf32 mma.sync, 128x256 CTA tile)
    sgemm_mma<<<dim3(D_DIM / 256, M / 128), 256, GSMEM_BYTES>>>(
        att, w_proj, outp, M, D_DIM, D_DIM);
}

// round 6
// speedup vs baseline: 3.8436x; 1.0835x over previous
#include <cuda_runtime.h>
#include <math.h>
#include <cstdint>

#define B_SZ   4
#define S_LEN  2048
#define D_DIM  1024
#define NH     16
#define HD_    64
#define QKV_LD 3072

// Scratch (no runtime allocation allowed). All tf32-bit buffers are uint32.
__device__ uint32_t g_xa[(size_t)B_SZ * S_LEN * D_DIM];   // x  (tf32)
__device__ uint32_t g_wa[(size_t)QKV_LD * D_DIM];         // w_attn (tf32)
__device__ uint32_t g_wp[(size_t)D_DIM * D_DIM];          // w_proj (tf32)
__device__ uint32_t g_qkv[(size_t)B_SZ * S_LEN * QKV_LD]; // qkv (tf32)
__device__ uint32_t g_att[(size_t)B_SZ * S_LEN * D_DIM];  // attn out (tf32)

// ---------------------------------------------------------------------------
// helpers (target-neutral; plain sm_103)
// ---------------------------------------------------------------------------
__device__ __forceinline__ uint32_t cvt_tf32(float f) {
    uint32_t r;
    asm("cvt.rna.tf32.f32 %0, %1;" : "=r"(r) : "f"(f));
    return r;
}

__device__ __forceinline__ uint32_t smem_u32(const void* p) {
    uint32_t a;
    asm("{ .reg .u64 t; cvta.to.shared.u64 t, %1; cvt.u32.u64 %0, t; }"
        : "=r"(a) : "l"(p));
    return a;
}

#define CP_ASYNC16(dst_u32, src_ptr)                                          \
    asm volatile("cp.async.cg.shared.global [%0], [%1], 16;"                  \
                 :: "r"(dst_u32), "l"(src_ptr))
#define CP_COMMIT() asm volatile("cp.async.commit_group;" ::: "memory")
#define CP_WAIT(n)  asm volatile("cp.async.wait_group %0;" :: "n"(n) : "memory")

#define MMA_TF32(d0, d1, d2, d3, a0, a1, a2, a3, b0, b1)                      \
    asm volatile(                                                             \
        "mma.sync.aligned.m16n8k8.row.col.f32.tf32.tf32.f32 "                 \
        "{%0,%1,%2,%3}, {%4,%5,%6,%7}, {%8,%9}, {%0,%1,%2,%3};"               \
        : "+f"(d0), "+f"(d1), "+f"(d2), "+f"(d3)                              \
        : "r"(a0), "r"(a1), "r"(a2), "r"(a3), "r"(b0), "r"(b1))

// ---------------------------------------------------------------------------
// One-shot tf32 conversion of x, w_attn, w_proj (bandwidth-bound, ~13us).
// ---------------------------------------------------------------------------
#define NX4  (B_SZ * S_LEN * D_DIM / 4)     // 2097152
#define NWA4 (QKV_LD * D_DIM / 4)           // 786432
#define NWP4 (D_DIM * D_DIM / 4)            // 262144
#define NCVT4 (NX4 + NWA4 + NWP4)

__global__ __launch_bounds__(256)
void cvt_inputs(const float4* __restrict__ x, const float4* __restrict__ wa,
                const float4* __restrict__ wp) {
    const int i = blockIdx.x * 256 + threadIdx.x;
    float4 v;
    uint4* dst;
    if (i < NX4)            { v = x[i];               dst = (uint4*)g_xa + i; }
    else if (i < NX4 + NWA4){ v = wa[i - NX4];        dst = (uint4*)g_wa + (i - NX4); }
    else                    { v = wp[i - NX4 - NWA4]; dst = (uint4*)g_wp + (i - NX4 - NWA4); }
    uint4 o;
    o.x = cvt_tf32(v.x); o.y = cvt_tf32(v.y);
    o.z = cvt_tf32(v.z); o.w = cvt_tf32(v.w);
    *dst = o;
}

// ---------------------------------------------------------------------------
// Tensor-core GEMM (tf32 mma.sync, NT): C[M,N] = A[M,K] * B[N,K]^T.
// A,B are PRE-CONVERTED tf32 bits. cp.async producer, 4-stage pipeline.
// 256 threads (8 warps as 2x4), CTA tile 128x256, warp tile 64x64.
// OUT_TF32: epilogue emits tf32 bits (for qkv) vs plain fp32 (final out).
// ---------------------------------------------------------------------------
#define SROW 36
#define ASTG (128 * SROW)
#define BSTG (256 * SROW)
#define STG_BYTES ((ASTG + BSTG) * 4)          // 55296
#define GSMEM_BYTES (4 * STG_BYTES)            // 221184

template <bool OUT_TF32>
__global__ __launch_bounds__(256)
void sgemm_tc(const uint32_t* __restrict__ A, const uint32_t* __restrict__ B,
              void* __restrict__ Cv, int M, int N, int K) {
    extern __shared__ __align__(16) uint32_t sm[];
    const uint32_t sbase = smem_u32(sm);

    const int tid  = threadIdx.x;
    const int wid  = tid >> 5;
    const int lane = tid & 31;
    const int g    = lane >> 2;
    const int t    = lane & 3;
    const int row0 = blockIdx.y << 7;
    const int col0 = blockIdx.x << 8;
    const int warp_m = (wid & 1) * 64;
    const int warp_n = (wid >> 1) * 64;

    const int rbase = tid >> 3;       // 0..31
    const int c4    = (tid & 7) * 4;  // 0..28

    const uint32_t* Abase = A + (size_t)(row0 + rbase) * K + c4;
    const uint32_t* Bbase = B + (size_t)(col0 + rbase) * K + c4;
    // per-thread smem dst offsets (bytes) within a stage
    const uint32_t adst = sbase + (uint32_t)(rbase * SROW + c4) * 4;
    const uint32_t bdst = sbase + (uint32_t)(ASTG + rbase * SROW + c4) * 4;

    const int KT = K >> 5;

    float acc[4][8][4];
#pragma unroll
    for (int i = 0; i < 4; i++)
#pragma unroll
        for (int j = 0; j < 8; j++)
#pragma unroll
            for (int k = 0; k < 4; k++) acc[i][j][k] = 0.f;

    // prologue: issue stages 0..2
#pragma unroll
    for (int s = 0; s < 3; s++) {
        const int kb = s << 5;
        const uint32_t so = (uint32_t)s * STG_BYTES;
#pragma unroll
        for (int i = 0; i < 4; i++)
            CP_ASYNC16(adst + so + i * (32 * SROW * 4), Abase + (size_t)(32 * i) * K + kb);
#pragma unroll
        for (int i = 0; i < 8; i++)
            CP_ASYNC16(bdst + so + i * (32 * SROW * 4), Bbase + (size_t)(32 * i) * K + kb);
        CP_COMMIT();
    }

    for (int kt = 0; kt < KT; kt++) {
        CP_WAIT(2);
        __syncthreads();

        const uint32_t* Asb = sm + (size_t)(kt & 3) * (STG_BYTES / 4);
        const uint32_t* Bsb = Asb + ASTG;

#pragma unroll
        for (int ks = 0; ks < 4; ks++) {
            uint32_t af[4][4], bf[8][2];
#pragma unroll
            for (int mt = 0; mt < 4; mt++) {
                const uint32_t* ap = Asb + (warp_m + mt * 16 + g) * SROW + ks * 8 + t;
                af[mt][0] = ap[0];
                af[mt][1] = ap[8 * SROW];
                af[mt][2] = ap[4];
                af[mt][3] = ap[8 * SROW + 4];
            }
#pragma unroll
            for (int nt = 0; nt < 8; nt++) {
                const uint32_t* bp = Bsb + (warp_n + nt * 8 + g) * SROW + ks * 8 + t;
                bf[nt][0] = bp[0];
                bf[nt][1] = bp[4];
            }
#pragma unroll
            for (int mt = 0; mt < 4; mt++)
#pragma unroll
                for (int nt = 0; nt < 8; nt++)
                    MMA_TF32(acc[mt][nt][0], acc[mt][nt][1],
                             acc[mt][nt][2], acc[mt][nt][3],
                             af[mt][0], af[mt][1], af[mt][2], af[mt][3],
                             bf[nt][0], bf[nt][1]);
        }

        if (kt + 3 < KT) {
            const int kb = (kt + 3) << 5;
            const uint32_t so = (uint32_t)((kt + 3) & 3) * STG_BYTES;
#pragma unroll
            for (int i = 0; i < 4; i++)
                CP_ASYNC16(adst + so + i * (32 * SROW * 4), Abase + (size_t)(32 * i) * K + kb);
#pragma unroll
            for (int i = 0; i < 8; i++)
                CP_ASYNC16(bdst + so + i * (32 * SROW * 4), Bbase + (size_t)(32 * i) * K + kb);
        }
        CP_COMMIT();   // commit (possibly empty) to keep group accounting uniform
    }

    // epilogue
#pragma unroll
    for (int mt = 0; mt < 4; mt++) {
        const int r_lo = row0 + warp_m + mt * 16 + g;
#pragma unroll
        for (int nt = 0; nt < 8; nt++) {
            const int cc = col0 + warp_n + nt * 8 + 2 * t;
            if (OUT_TF32) {
                uint32_t* C = (uint32_t*)Cv;
                *(uint2*)(C + (size_t)r_lo * N + cc) =
                    make_uint2(cvt_tf32(acc[mt][nt][0]), cvt_tf32(acc[mt][nt][1]));
                *(uint2*)(C + (size_t)(r_lo + 8) * N + cc) =
                    make_uint2(cvt_tf32(acc[mt][nt][2]), cvt_tf32(acc[mt][nt][3]));
            } else {
                float* C = (float*)Cv;
                *(float2*)(C + (size_t)r_lo * N + cc) =
                    make_float2(acc[mt][nt][0], acc[mt][nt][1]);
                *(float2*)(C + (size_t)(r_lo + 8) * N + cc) =
                    make_float2(acc[mt][nt][2], acc[mt][nt][3]);
            }
        }
    }
}

// ---------------------------------------------------------------------------
// Causal flash attention, tf32 mma.sync. qkv holds tf32 bits (no cvt in
// loads). K/V tiles via cp.async. Output written as tf32 bits for proj GEMM.
// ---------------------------------------------------------------------------
#define ATT_SROW 68
#define ATT_VS   (64 * ATT_SROW)
#define ATT_PS   (2 * 64 * ATT_SROW)
#define ATT_SMEM_BYTES ((2 * 64 * ATT_SROW + 128 * ATT_SROW) * 4)

__global__ __launch_bounds__(256)
void attn_mma(const uint32_t* __restrict__ qkv, uint32_t* __restrict__ out) {
    extern __shared__ __align__(16) uint32_t sm2[];
    const uint32_t s2base = smem_u32(sm2);

    const int bh = blockIdx.y;
    const int b  = bh >> 4;
    const int h  = bh & 15;
    const int q0 = (int)(gridDim.x - 1 - blockIdx.x) << 7;

    const int tid  = threadIdx.x;
    const int wid  = tid >> 5;
    const int lane = tid & 31;
    const int g    = lane >> 2;
    const int t    = lane & 3;

    const size_t row_base = (size_t)b * S_LEN;

    // ---- stage Q tile (already tf32) ----
#pragma unroll
    for (int i = 0; i < 8; i++) {
        const int idx = tid + i * 256;
        const int r   = idx >> 4;
        const int c4  = (idx & 15) * 4;
        uint4 v = *(const uint4*)(qkv + (row_base + q0 + r) * QKV_LD + h * HD_ + c4);
        uint32_t* p = sm2 + ATT_PS + r * ATT_SROW + c4;
        p[0] = v.x; p[1] = v.y; p[2] = v.z; p[3] = v.w;
    }
    __syncthreads();

    uint32_t qf[8][4];
    {
        const uint32_t* qs = sm2 + ATT_PS + (wid * 16 + g) * ATT_SROW;
#pragma unroll
        for (int ks = 0; ks < 8; ks++) {
            const uint32_t* p = qs + ks * 8 + t;
            qf[ks][0] = p[0];
            qf[ks][1] = p[8 * ATT_SROW];
            qf[ks][2] = p[4];
            qf[ks][3] = p[8 * ATT_SROW + 4];
        }
    }

    float m0 = -1e30f, m1 = -1e30f, l0 = 0.f, l1 = 0.f;
    float o[8][4];
#pragma unroll
    for (int nt = 0; nt < 8; nt++)
#pragma unroll
        for (int j = 0; j < 4; j++) o[nt][j] = 0.f;

    uint32_t* const pw = sm2 + ATT_PS + wid * (16 * ATT_SROW);
    const int myrowmax = q0 + wid * 16 + 15;
    const int nkt = (q0 >> 6) + 2;
    const unsigned FULL = 0xffffffffu;

    // per-thread K/V cp.async addressing
    const int lr  = tid >> 2;
    const int lcb = (tid & 3) * 16;
    const uint32_t kdst = s2base + (uint32_t)(lr * ATT_SROW + lcb) * 4;
    const uint32_t vdst = s2base + (uint32_t)(ATT_VS + lr * ATT_SROW + lcb) * 4;

    for (int kt = 0; kt < nkt; kt++) {
        const int k0 = kt << 6;

        // ---- load K,V tiles via cp.async (raw tf32 copy) ----
        {
            const uint32_t* kg = qkv + (row_base + k0 + lr) * QKV_LD + D_DIM + h * HD_ + lcb;
#pragma unroll
            for (int i = 0; i < 4; i++) {
                CP_ASYNC16(kdst + i * 16, kg + i * 4);
                CP_ASYNC16(vdst + i * 16, kg + D_DIM + i * 4);
            }
            CP_COMMIT();
            CP_WAIT(0);
        }
        __syncthreads();

        if (k0 <= myrowmax) {   // warp-uniform: tile not fully masked
            // ---- scores S = Q K^T ----
            float acc[8][4];
#pragma unroll
            for (int nt = 0; nt < 8; nt++)
#pragma unroll
                for (int j = 0; j < 4; j++) acc[nt][j] = 0.f;

#pragma unroll
            for (int ks = 0; ks < 8; ks++) {
                uint32_t bf[8][2];
#pragma unroll
                for (int nt = 0; nt < 8; nt++) {
                    const uint32_t* bp = sm2 + (nt * 8 + g) * ATT_SROW + ks * 8 + t;
                    bf[nt][0] = bp[0];
                    bf[nt][1] = bp[4];
                }
#pragma unroll
                for (int nt = 0; nt < 8; nt++)
                    MMA_TF32(acc[nt][0], acc[nt][1], acc[nt][2], acc[nt][3],
                             qf[ks][0], qf[ks][1], qf[ks][2], qf[ks][3],
                             bf[nt][0], bf[nt][1]);
            }

            // ---- scale + causal mask ----
            const int r0 = q0 + wid * 16 + g;
            const int r1 = r0 + 8;
            const bool needmask = (k0 + 63 > q0 + wid * 16);
#pragma unroll
            for (int nt = 0; nt < 8; nt++) {
                const int col = k0 + nt * 8 + 2 * t;
                acc[nt][0] *= 0.125f; acc[nt][1] *= 0.125f;
                acc[nt][2] *= 0.125f; acc[nt][3] *= 0.125f;
                if (needmask) {
                    if (col > r0)     acc[nt][0] = -1e30f;
                    if (col + 1 > r0) acc[nt][1] = -1e30f;
                    if (col > r1)     acc[nt][2] = -1e30f;
                    if (col + 1 > r1) acc[nt][3] = -1e30f;
                }
            }

            // ---- online softmax ----
            float mt0 = -1e30f, mt1 = -1e30f;
#pragma unroll
            for (int nt = 0; nt < 8; nt++) {
                mt0 = fmaxf(mt0, fmaxf(acc[nt][0], acc[nt][1]));
                mt1 = fmaxf(mt1, fmaxf(acc[nt][2], acc[nt][3]));
            }
            mt0 = fmaxf(mt0, __shfl_xor_sync(FULL, mt0, 1));
            mt0 = fmaxf(mt0, __shfl_xor_sync(FULL, mt0, 2));
            mt1 = fmaxf(mt1, __shfl_xor_sync(FULL, mt1, 1));
            mt1 = fmaxf(mt1, __shfl_xor_sync(FULL, mt1, 2));

            const float mn0 = fmaxf(m0, mt0);
            const float mn1 = fmaxf(m1, mt1);
            const float c0 = __expf(m0 - mn0);
            const float c1 = __expf(m1 - mn1);
            float s0 = 0.f, s1 = 0.f;
#pragma unroll
            for (int nt = 0; nt < 8; nt++) {
                acc[nt][0] = __expf(acc[nt][0] - mn0); s0 += acc[nt][0];
                acc[nt][1] = __expf(acc[nt][1] - mn0); s0 += acc[nt][1];
                acc[nt][2] = __expf(acc[nt][2] - mn1); s1 += acc[nt][2];
                acc[nt][3] = __expf(acc[nt][3] - mn1); s1 += acc[nt][3];
            }
            s0 += __shfl_xor_sync(FULL, s0, 1);
            s0 += __shfl_xor_sync(FULL, s0, 2);
            s1 += __shfl_xor_sync(FULL, s1, 1);
            s1 += __shfl_xor_sync(FULL, s1, 2);
            l0 = l0 * c0 + s0; m0 = mn0;
            l1 = l1 * c1 + s1; m1 = mn1;
#pragma unroll
            for (int nt = 0; nt < 8; nt++) {
                o[nt][0] *= c0; o[nt][1] *= c0;
                o[nt][2] *= c1; o[nt][3] *= c1;
            }

            // ---- P -> warp-private smem (tf32) ----
#pragma unroll
            for (int nt = 0; nt < 8; nt++) {
                uint32_t* p0 = pw + g * ATT_SROW + nt * 8 + 2 * t;
                uint32_t* p1 = pw + (g + 8) * ATT_SROW + nt * 8 + 2 * t;
                p0[0] = cvt_tf32(acc[nt][0]); p0[1] = cvt_tf32(acc[nt][1]);
                p1[0] = cvt_tf32(acc[nt][2]); p1[1] = cvt_tf32(acc[nt][3]);
            }
            __syncwarp();

            // ---- O += P V ----
#pragma unroll
            for (int ks = 0; ks < 8; ks++) {
                const uint32_t* pa = pw + g * ATT_SROW + ks * 8 + t;
                const uint32_t a0 = pa[0];
                const uint32_t a1 = pa[8 * ATT_SROW];
                const uint32_t a2 = pa[4];
                const uint32_t a3 = pa[8 * ATT_SROW + 4];
#pragma unroll
                for (int nt = 0; nt < 8; nt++) {
                    const uint32_t* vb = sm2 + ATT_VS + (ks * 8 + t) * ATT_SROW + nt * 8 + g;
                    const uint32_t b0 = vb[0];
                    const uint32_t b1 = vb[4 * ATT_SROW];
                    MMA_TF32(o[nt][0], o[nt][1], o[nt][2], o[nt][3],
                             a0, a1, a2, a3, b0, b1);
                }
            }
        }
        __syncthreads();
    }

    // ---- epilogue: tf32 bits for the proj GEMM ----
    const float i0 = 1.0f / l0;
    const float i1 = 1.0f / l1;
    const size_t r0 = row_base + q0 + wid * 16 + g;
#pragma unroll
    for (int nt = 0; nt < 8; nt++) {
        const int col = h * HD_ + nt * 8 + 2 * t;
        *(uint2*)(out + r0 * D_DIM + col) =
            make_uint2(cvt_tf32(o[nt][0] * i0), cvt_tf32(o[nt][1] * i0));
        *(uint2*)(out + (r0 + 8) * D_DIM + col) =
            make_uint2(cvt_tf32(o[nt][2] * i1), cvt_tf32(o[nt][3] * i1));
    }
}

// ---------------------------------------------------------------------------
extern "C" void kernel_launch(void* const* d_in, const int* in_sizes, int n_in,
                              void* d_out, int out_size) {
    const float* x      = (const float*)d_in[0];  // [B, S, D]
    const float* w_attn = (const float*)d_in[1];  // [3D, D]
    const float* w_proj = (const float*)d_in[2];  // [D, D]
    float* outp         = (float*)d_out;          // [B, S, D]

    void *p_xa, *p_wa, *p_wp, *p_qkv, *p_att;
    cudaGetSymbolAddress(&p_xa, g_xa);
    cudaGetSymbolAddress(&p_wa, g_wa);
    cudaGetSymbolAddress(&p_wp, g_wp);
    cudaGetSymbolAddress(&p_qkv, g_qkv);
    cudaGetSymbolAddress(&p_att, g_att);

    const int M = B_SZ * S_LEN;  // 8192

    cudaFuncSetAttribute(sgemm_tc<true>,
                         cudaFuncAttributeMaxDynamicSharedMemorySize, GSMEM_BYTES);
    cudaFuncSetAttribute(sgemm_tc<false>,
                         cudaFuncAttributeMaxDynamicSharedMemorySize, GSMEM_BYTES);
    cudaFuncSetAttribute(attn_mma,
                         cudaFuncAttributeMaxDynamicSharedMemorySize, ATT_SMEM_BYTES);

    // 0) one-shot tf32 conversion of inputs
    cvt_inputs<<<NCVT4 / 256, 256>>>((const float4*)x, (const float4*)w_attn,
                                     (const float4*)w_proj);

    // 1) QKV = X @ W_attn^T  -> tf32 bits
    sgemm_tc<true><<<dim3(QKV_LD / 256, M / 128), 256, GSMEM_BYTES>>>(
        (const uint32_t*)p_xa, (const uint32_t*)p_wa, p_qkv, M, QKV_LD, D_DIM);

    // 2) causal attention -> att (tf32 bits)
    attn_mma<<<dim3(S_LEN / 128, B_SZ * NH), 256, ATT_SMEM_BYTES>>>(
        (const uint32_t*)p_qkv, (uint32_t*)p_att);

    // 3) out = att @ W_proj^T  -> fp32
    sgemm_tc<false><<<dim3(D_DIM / 256, M / 128), 256, GSMEM_BYTES>>>(
        (const uint32_t*)p_att, (const uint32_t*)p_wp, outp, M, D_DIM, D_DIM);
}